// round 15
// baseline (speedup 1.0000x reference)
#include <cuda_runtime.h>
#include <cuda_bf16.h>
#include <math.h>

#define Bb  2
#define NN  8192
#define CA  128
#define CS  384
#define CZ  16
#define HH  4
#define DD  32
#define NQ  32
#define NK  128
#define NB  3
#define WW  256
#define HID 256
#define TT  (Bb*NN)
#define ROWS 2097152
#define NG  2304

typedef unsigned short ushort_t;

// ---------------- scratch ----------------
__device__ ushort_t g_slnH[(size_t)TT*CS], g_slnL[(size_t)TT*CS];
__device__ float    g_gatesP[(size_t)TT*NG];
__device__ float    g_biasbuf[(size_t)NB*HH*ROWS];
__device__ ushort_t g_alnH[(size_t)TT*CA], g_alnL[(size_t)TT*CA];
__device__ ushort_t g_tlnH[(size_t)TT*CA], g_tlnL[(size_t)TT*CA];
__device__ float    g_qkvg[(size_t)TT*512];
__device__ ushort_t g_attH[(size_t)TT*CA], g_attL[(size_t)TT*CA];
__device__ float    g_ao [(size_t)TT*CA];
__device__ float    g_a  [(size_t)TT*CA];
__device__ float    g_hid[(size_t)TT*512];
// pre-split weights: [plane][k][n] bf16
__device__ ushort_t g_wgateP[(size_t)2*CS*NG];
__device__ ushort_t g_wqkvgP[(size_t)NB*2*128*512];
__device__ ushort_t g_whidP [(size_t)NB*2*128*512];
__device__ ushort_t g_wwoP  [(size_t)NB*2*128*128];
__device__ ushort_t g_wtwoP [(size_t)NB*2*256*128];
__device__ float    g_bgate[NG];
__device__ float    g_bqkvg[NB*512];

__device__ __forceinline__ float sigm(float x){ return 1.f/(1.f+__expf(-x)); }

__device__ __forceinline__ void split1(float x, ushort_t &hi, ushort_t &lo){
    __nv_bfloat16 h = __float2bfloat16(x);
    hi = __bfloat16_as_ushort(h);
    lo = __bfloat16_as_ushort(__float2bfloat16(x - __bfloat162float(h)));
}
__device__ __forceinline__ void split2(float x0, float x1, unsigned &hi, unsigned &lo){
    ushort_t h0,l0,h1,l1;
    split1(x0,h0,l0); split1(x1,h1,l1);
    hi = (unsigned)h0 | ((unsigned)h1<<16);
    lo = (unsigned)l0 | ((unsigned)l1<<16);
}

__device__ __forceinline__ void mma_bf16(float* c, const unsigned* a, const unsigned* b){
    asm volatile(
        "mma.sync.aligned.m16n8k16.row.col.f32.bf16.bf16.f32 "
        "{%0,%1,%2,%3},{%4,%5,%6,%7},{%8,%9},{%0,%1,%2,%3};"
        : "+f"(c[0]), "+f"(c[1]), "+f"(c[2]), "+f"(c[3])
        : "r"(a[0]), "r"(a[1]), "r"(a[2]), "r"(a[3]), "r"(b[0]), "r"(b[1]));
}
__device__ __forceinline__ void ldsm_x4(unsigned* r, unsigned addr){
    asm volatile("ldmatrix.sync.aligned.m8n8.x4.shared.b16 {%0,%1,%2,%3}, [%4];"
        : "=r"(r[0]),"=r"(r[1]),"=r"(r[2]),"=r"(r[3]) : "r"(addr));
}
__device__ __forceinline__ void ldsm_x4_t(unsigned* r, unsigned addr){
    asm volatile("ldmatrix.sync.aligned.m8n8.x4.trans.shared.b16 {%0,%1,%2,%3}, [%4];"
        : "=r"(r[0]),"=r"(r[1]),"=r"(r[2]),"=r"(r[3]) : "r"(addr));
}
__device__ __forceinline__ void cp16(unsigned saddr, const void* gaddr){
    asm volatile("cp.async.cg.shared.global [%0], [%1], 16;" :: "r"(saddr), "l"(gaddr));
}
#define CP_COMMIT() asm volatile("cp.async.commit_group;")
#define CP_WAIT0()  asm volatile("cp.async.wait_group 0;")

__device__ __forceinline__ void blockReduce2_128(float& s, float& q){
    __shared__ float sb[8];
    #pragma unroll
    for (int o=16;o;o>>=1){
        s += __shfl_xor_sync(0xffffffffu, s, o);
        q += __shfl_xor_sync(0xffffffffu, q, o);
    }
    int wid = threadIdx.x>>5;
    if ((threadIdx.x&31)==0){ sb[wid*2]=s; sb[wid*2+1]=q; }
    __syncthreads();
    s = sb[0]+sb[2]+sb[4]+sb[6];
    q = sb[1]+sb[3]+sb[5]+sb[7];
}

// ---------------- weight packing (layout [plane][k][n]) ----------------
__global__ void pack_kernel(
    const float* __restrict__ aw,  const float* __restrict__ ashw,
    const float* __restrict__ sgw, const float* __restrict__ tsw,
    const float* __restrict__ tshw,const float* __restrict__ tsgw,
    const float* __restrict__ a_sb,const float* __restrict__ sg_b,
    const float* __restrict__ ts_b,const float* __restrict__ tsg_b,
    const float* __restrict__ wq,  const float* __restrict__ bq,
    const float* __restrict__ wk,  const float* __restrict__ wv,
    const float* __restrict__ wg,  const float* __restrict__ twa,
    const float* __restrict__ twb, const float* __restrict__ wo,
    const float* __restrict__ two)
{
    int idx = blockIdx.x*256 + threadIdx.x;
    const int R1 = CS*NG;
    const int R2 = NB*128*512;
    const int R3 = NB*128*512;
    const int R4 = NB*128*128;
    const int R5 = NB*256*128;
    ushort_t h,l;
    if (idx < R1){
        int k = idx / NG, r = idx % NG;
        int gi = r>>7, c = r&127;
        int i = gi/6, g = gi - i*6;
        const float* src;
        switch(g){
            case 0: src=aw; break; case 1: src=ashw; break; case 2: src=sgw; break;
            case 3: src=tsw; break; case 4: src=tshw; break; default: src=tsgw; break;
        }
        split1(src[((size_t)i*CS + k)*CA + c], h, l);
        g_wgateP[idx] = h; g_wgateP[(size_t)CS*NG + idx] = l;
        return;
    }
    idx -= R1;
    if (idx < R2){
        int blk = idx/(128*512), r = idx%(128*512);
        int k = r>>9, j = r&511;
        float v;
        if (j < 128)      v = wq[((size_t)blk*CA + k)*128 + j];
        else if (j < 256) v = wk[((size_t)blk*CA + k)*128 + (j-128)];
        else if (j < 384) v = wv[((size_t)blk*CA + k)*128 + (j-256)];
        else              v = wg[((size_t)blk*CA + k)*128 + (j-384)];
        split1(v,h,l);
        size_t base = (size_t)blk*2*128*512;
        g_wqkvgP[base + r] = h; g_wqkvgP[base + 128*512 + r] = l;
        return;
    }
    idx -= R2;
    if (idx < R3){
        int blk = idx/(128*512), r = idx%(128*512);
        int k = r>>9, j = r&511;
        float v = (j<256) ? twa[((size_t)blk*CA + k)*256 + j]
                          : twb[((size_t)blk*CA + k)*256 + (j-256)];
        split1(v,h,l);
        size_t base = (size_t)blk*2*128*512;
        g_whidP[base + r] = h; g_whidP[base + 128*512 + r] = l;
        return;
    }
    idx -= R3;
    if (idx < R4){
        int blk = idx/(128*128), r = idx%(128*128);
        int k = r>>7, n = r&127;
        split1(wo[(size_t)blk*CA*CA + (size_t)k*CA + n], h, l);
        size_t base = (size_t)blk*2*128*128;
        g_wwoP[base + r] = h; g_wwoP[base + 128*128 + r] = l;
        return;
    }
    idx -= R4;
    if (idx < R5){
        int blk = idx/(256*128), r = idx%(256*128);
        int k = r>>7, n = r&127;
        split1(two[(size_t)blk*HID*CA + (size_t)k*CA + n], h, l);
        size_t base = (size_t)blk*2*256*128;
        g_wtwoP[base + r] = h; g_wtwoP[base + 256*128 + r] = l;
        return;
    }
    idx -= R5;
    if (idx < NG){
        int gi = idx>>7, c = idx&127;
        int i = gi/6, g = gi - i*6;
        float v = 0.f;
        if (g==0) v = a_sb[i*128+c];
        else if (g==2) v = sg_b[i*128+c];
        else if (g==3) v = ts_b[i*128+c];
        else if (g==5) v = tsg_b[i*128+c];
        g_bgate[idx] = v;
        return;
    }
    idx -= NG;
    if (idx < NB*512){
        int blk = idx>>9, j = idx&511;
        g_bqkvg[idx] = (j<128) ? bq[blk*128 + j] : 0.f;
    }
}

// ---------------- K1: layernorm of s ----------------
__global__ void sln_kernel(const float* __restrict__ s){
    int t = blockIdx.x, tid = threadIdx.x;
    const float* row = s + (size_t)t*CS;
    float v0=row[tid], v1=row[tid+128], v2=row[tid+256];
    float su=v0+v1+v2, sq=v0*v0+v1*v1+v2*v2;
    blockReduce2_128(su,sq);
    float mean = su*(1.f/CS);
    float var  = sq*(1.f/CS) - mean*mean;
    float inv  = rsqrtf(var + 1e-5f);
    size_t base = (size_t)t*CS;
    ushort_t h,l;
    split1((v0-mean)*inv,h,l); g_slnH[base+tid]=h;     g_slnL[base+tid]=l;
    split1((v1-mean)*inv,h,l); g_slnH[base+tid+128]=h; g_slnL[base+tid+128]=l;
    split1((v2-mean)*inv,h,l); g_slnH[base+tid+256]=h; g_slnL[base+tid+256]=l;
}

// ---------------- K3: pair bias ----------------
__global__ void bias_kernel(const float* __restrict__ p, const float* __restrict__ lnz_w,
                            const float* __restrict__ lnz_b, const float* __restrict__ wb){
    __shared__ float s_w[NB*CZ], s_b[NB*CZ], s_wb[NB*CZ*HH];
    int tid = threadIdx.x;
    if (tid < NB*CZ){ s_w[tid]=lnz_w[tid]; s_b[tid]=lnz_b[tid]; }
    if (tid < NB*CZ*HH) s_wb[tid]=wb[tid];
    __syncthreads();
    size_t r = (size_t)blockIdx.x*blockDim.x + tid;
    if (r >= (size_t)ROWS) return;
    const float4* p4 = (const float4*)(p + r*CZ);
    float z[16];
    float4 q0=p4[0], q1=p4[1], q2=p4[2], q3=p4[3];
    z[0]=q0.x; z[1]=q0.y; z[2]=q0.z; z[3]=q0.w;
    z[4]=q1.x; z[5]=q1.y; z[6]=q1.z; z[7]=q1.w;
    z[8]=q2.x; z[9]=q2.y; z[10]=q2.z; z[11]=q2.w;
    z[12]=q3.x; z[13]=q3.y; z[14]=q3.z; z[15]=q3.w;
    float su=0, sq=0;
    #pragma unroll
    for (int c=0;c<16;c++){ su+=z[c]; sq+=z[c]*z[c]; }
    float mean=su*(1.f/16.f), var=sq*(1.f/16.f)-mean*mean;
    float inv=rsqrtf(var+1e-5f);
    #pragma unroll
    for (int c=0;c<16;c++) z[c]=(z[c]-mean)*inv;
    #pragma unroll
    for (int i=0;i<NB;i++){
        float o0=0,o1=0,o2=0,o3=0;
        #pragma unroll
        for (int c=0;c<16;c++){
            float zz = z[c]*s_w[i*16+c] + s_b[i*16+c];
            const float* w4 = &s_wb[(i*16+c)*4];
            o0 += zz*w4[0]; o1 += zz*w4[1]; o2 += zz*w4[2]; o3 += zz*w4[3];
        }
        size_t base = ((size_t)i*HH)*ROWS + r;
        g_biasbuf[base]        = o0;
        g_biasbuf[base+ROWS]   = o1;
        g_biasbuf[base+2*(size_t)ROWS] = o2;
        g_biasbuf[base+3*(size_t)ROWS] = o3;
    }
}

// ---------------- K4: LN(a) + modulations ----------------
__global__ void lnmod_kernel(const float* __restrict__ a, int blk){
    int t = blockIdx.x, c = threadIdx.x;
    float x = a[(size_t)t*CA + c];
    float su=x, sq=x*x;
    blockReduce2_128(su,sq);
    float mean=su*(1.f/CA), var=sq*(1.f/CA)-mean*mean;
    float xn=(x-mean)*rsqrtf(var+1e-5f);
    size_t base = (size_t)t*NG;
    float sc  = g_gatesP[base + (blk*6+0)*128 + c];
    float sh_ = g_gatesP[base + (blk*6+1)*128 + c];
    float tsc = g_gatesP[base + (blk*6+3)*128 + c];
    float tsh = g_gatesP[base + (blk*6+4)*128 + c];
    size_t o=(size_t)t*CA+c;
    ushort_t h,l;
    split1(sc*xn + sh_, h, l); g_alnH[o]=h; g_alnL[o]=l;
    split1(tsc*xn + tsh, h, l); g_tlnH[o]=h; g_tlnL[o]=l;
}

// ---------------- GEMM: 3xBF16 m16n8k16 + ldmatrix + cp.async, BK=32, 2-stage, BM=64 ----------------
// Optional second task: CTAs with blockIdx.x >= nsplit use (AH2/AL2, BP2, biasv2, sigmask2, C2).
#define AS_  40
#define BSr  136
#define APL (64*AS_)
#define BPL (32*BSr)
#define BUFH (2*APL + 2*BPL)
#define NSTG 2
#define GEMM_SMEM (NSTG*BUFH*2)
template<bool GLU>
__global__ void __launch_bounds__(256, GLU?2:3) gemm_kernel(
        const ushort_t* __restrict__ AHp, const ushort_t* __restrict__ ALp, int lda,
        const float* __restrict__ Af, const float* __restrict__ A2f, int ldaf,
        const ushort_t* __restrict__ BPp,
        const float* __restrict__ biasvp, unsigned sigmaskp,
        const float* __restrict__ mulp, int ldmul,
        const float* __restrict__ addp, int ldadd,
        float* __restrict__ Cp, int M, int N, int K,
        const ushort_t* AH2, const ushort_t* AL2, const ushort_t* BP2,
        const float* biasv2, unsigned sigmask2, float* C2, int nsplit){
    extern __shared__ __align__(16) ushort_t sh[];
    const ushort_t* AH = AHp; const ushort_t* AL = ALp; const ushort_t* BP = BPp;
    const float* biasv = biasvp; unsigned sigmask = sigmaskp; float* C = Cp;
    int bx = blockIdx.x;
    if (AH2 && bx >= nsplit){
        AH = AH2; AL = AL2; BP = BP2; biasv = biasv2; sigmask = sigmask2; C = C2;
        bx -= nsplit;
    }
    int n0 = bx*128, m0 = blockIdx.y*64;
    int tid = threadIdx.x, lane = tid&31, wid = tid>>5;
    int g = lane>>2, tig = lane&3;
    int wm = (wid&1)*32, wn = (wid>>1)*32;
    float acc[2][4][4] = {};
    const int nit = K>>5;
    unsigned sbase = (unsigned)__cvta_generic_to_shared(sh);

    // A cp.async mapping (non-GLU)
    int apl_ = tid>>7, ac = tid&127;
    int arow1 = ac>>2, aq = ac&3;
    int arow2 = arow1 + 32;
    const ushort_t* AsrcP = 0;
    unsigned adst1 = 0, adst2 = 0;
    // A register path (GLU)
    int ar = tid>>2, akq = tid&3;
    const float *Apf = 0, *Gpf = 0;
    if (GLU){
        Apf = Af + (size_t)(m0+ar)*ldaf;
        Gpf = A2f + (size_t)(m0+ar)*ldaf;
    } else {
        AsrcP = (apl_ ? AL : AH) + (size_t)m0*lda;
        adst1 = (unsigned)((apl_*APL + arow1*AS_ + aq*8)*2);
        adst2 = (unsigned)((apl_*APL + arow2*AS_ + aq*8)*2);
    }
    // B cp.async mapping
    int bpl = tid>>7, bcid = tid&127;
    int brow = bcid>>4, bseg = (bcid&15)*8;
    const ushort_t* BsrcP = BP + (size_t)bpl*K*N + n0 + bseg;
    unsigned bdstb = (unsigned)((2*APL + bpl*BPL + bseg)*2);

    auto issue_tile = [&](int it){
        unsigned nb = (unsigned)((it&1)*BUFH*2);
        int kb = it*32;
        if (!GLU){
            cp16(sbase + nb + adst1, AsrcP + (size_t)(arow1)*lda + kb + aq*8);
            cp16(sbase + nb + adst2, AsrcP + (size_t)(arow2)*lda + kb + aq*8);
        }
        #pragma unroll
        for (int rr=0; rr<4; rr++){
            int kr = brow + rr*8;
            cp16(sbase + nb + bdstb + (unsigned)(kr*BSr*2),
                 BsrcP + (size_t)(kb + kr)*N);
        }
        CP_COMMIT();
    };
    auto store_A_glu = [&](int it){
        ushort_t* base = sh + (it&1)*BUFH;
        #pragma unroll
        for (int q=0; q<2; q++){
            int koff = it*32 + akq*4 + q*16;
            float4 v  = *(const float4*)(Apf + koff);
            float4 gv = *(const float4*)(Gpf + koff);
            v.x = v.x*sigm(v.x)*gv.x; v.y = v.y*sigm(v.y)*gv.y;
            v.z = v.z*sigm(v.z)*gv.z; v.w = v.w*sigm(v.w)*gv.w;
            unsigned h01,l01,h23,l23;
            split2(v.x,v.y,h01,l01);
            split2(v.z,v.w,h23,l23);
            int so = ar*AS_ + akq*4 + q*16;
            *(unsigned*)(base + so)           = h01;
            *(unsigned*)(base + so + 2)       = h23;
            *(unsigned*)(base + APL + so)     = l01;
            *(unsigned*)(base + APL + so + 2) = l23;
        }
    };

    // prologue
    issue_tile(0); if (GLU) store_A_glu(0);
    CP_WAIT0();
    __syncthreads();

    // ldmatrix per-thread byte offsets
    int mi = lane>>3, r8 = lane&7;
    unsigned aoff0 = (unsigned)(((wm + (mi&1)*8 + r8)*AS_ + (mi>>1)*8)*2);
    unsigned aoff1 = aoff0 + (unsigned)(16*AS_*2);
    unsigned boff0 = (unsigned)((((mi&1)*8 + r8)*BSr + wn + (mi>>1)*8)*2);
    unsigned boff1 = boff0 + 32;

    for (int it=0; it<nit; it++){
        if (it+1 < nit){
            issue_tile(it+1);
            if (GLU) store_A_glu(it+1);
        }
        unsigned bufb = sbase + (unsigned)((it&1)*BUFH*2);
        #pragma unroll
        for (int ks=0; ks<2; ks++){
            unsigned ka = bufb + (unsigned)(ks*32);
            unsigned kb = bufb + (unsigned)(ks*16*BSr*2);
            unsigned ah[2][4], alo[2][4], bh[2][4], bl[2][4];
            ldsm_x4(ah[0],  ka + aoff0);
            ldsm_x4(ah[1],  ka + aoff1);
            ldsm_x4(alo[0], ka + (unsigned)(APL*2) + aoff0);
            ldsm_x4(alo[1], ka + (unsigned)(APL*2) + aoff1);
            ldsm_x4_t(bh[0], kb + (unsigned)(2*APL*2) + boff0);
            ldsm_x4_t(bh[1], kb + (unsigned)(2*APL*2) + boff1);
            ldsm_x4_t(bl[0], kb + (unsigned)((2*APL+BPL)*2) + boff0);
            ldsm_x4_t(bl[1], kb + (unsigned)((2*APL+BPL)*2) + boff1);
            #pragma unroll
            for (int mt=0; mt<2; mt++){
                #pragma unroll
                for (int nt=0; nt<4; nt++){
                    const unsigned* bph = &bh[nt>>1][(nt&1)*2];
                    const unsigned* bpl_ = &bl[nt>>1][(nt&1)*2];
                    mma_bf16(acc[mt][nt], ah[mt],  bph);
                    mma_bf16(acc[mt][nt], ah[mt],  bpl_);
                    mma_bf16(acc[mt][nt], alo[mt], bph);
                }
            }
        }
        if (it+1 < nit) CP_WAIT0();
        __syncthreads();
    }

    // epilogue
    #pragma unroll
    for (int mt=0; mt<2; mt++){
        #pragma unroll
        for (int nt=0; nt<4; nt++){
            int row0 = m0 + wm + mt*16 + g;
            int row1 = row0 + 8;
            int col  = n0 + wn + nt*8 + 2*tig;
            float b0 = biasv ? biasv[col]   : 0.f;
            float b1 = biasv ? biasv[col+1] : 0.f;
            float e0 = acc[mt][nt][0] + b0, e1 = acc[mt][nt][1] + b1;
            float e2 = acc[mt][nt][2] + b0, e3 = acc[mt][nt][3] + b1;
            if ((sigmask >> (col>>7)) & 1u){ e0=sigm(e0); e1=sigm(e1); e2=sigm(e2); e3=sigm(e3); }
            size_t o0 = (size_t)row0*N + col, o1 = (size_t)row1*N + col;
            if (mulp){
                size_t u0 = (size_t)row0*ldmul + col, u1 = (size_t)row1*ldmul + col;
                e0*=mulp[u0]; e1*=mulp[u0+1]; e2*=mulp[u1]; e3*=mulp[u1+1];
            }
            if (addp){
                size_t u0 = (size_t)row0*ldadd + col, u1 = (size_t)row1*ldadd + col;
                e0+=addp[u0]; e1+=addp[u0+1]; e2+=addp[u1]; e3+=addp[u1+1];
            }
            *(float2*)&C[o0] = make_float2(e0,e1);
            *(float2*)&C[o1] = make_float2(e2,e3);
        }
    }
}

// ---------------- K6: windowed attention ----------------
__global__ void attn_kernel(int blk){
    __shared__ float qs[NQ*DD];
    __shared__ float kv[NK*33];
    __shared__ float lb[NQ*129];
    int w = blockIdx.x, h = blockIdx.y, b = blockIdx.z;
    int tid = threadIdx.x;
    size_t tokbase = (size_t)b*NN + (size_t)w*NQ;
    int kstart = w*NQ - 48;
    for (int i=tid; i<NQ*DD; i+=256){
        int r=i>>5, c=i&31;
        qs[i] = g_qkvg[(tokbase+r)*512 + h*DD + c];
    }
    for (int i=tid; i<NK*DD; i+=256){
        int r=i>>5, c=i&31;
        int src = kstart + r; src = min(max(src,0), NN-1);
        kv[r*33+c] = g_qkvg[((size_t)b*NN + src)*512 + 128 + h*DD + c];
    }
    const float* plane = g_biasbuf + ((size_t)blk*HH + h)*(size_t)ROWS;
    size_t rb = (((size_t)b*WW + w)*NQ)*NK;
    for (int i=tid; i<NQ*NK; i+=256){
        int q=i>>7, k=i&127;
        lb[q*129+k] = plane[rb + i];
    }
    __syncthreads();
    {
        int qt = tid>>5, kt = tid&31;
        float acc[4][4] = {};
        #pragma unroll
        for (int d=0; d<DD; d++){
            float qa[4], kb[4];
            #pragma unroll
            for (int j=0;j<4;j++) qa[j] = qs[(qt*4+j)*DD + d];
            #pragma unroll
            for (int l=0;l<4;l++) kb[l] = kv[(kt+32*l)*33 + d];
            #pragma unroll
            for (int j=0;j<4;j++)
                #pragma unroll
                for (int l=0;l<4;l++) acc[j][l] += qa[j]*kb[l];
        }
        const float isd = 0.17677669529663687f;
        #pragma unroll
        for (int j=0;j<4;j++){
            #pragma unroll
            for (int l=0;l<4;l++){
                int q = qt*4+j, k = kt+32*l;
                int src = kstart + k;
                float v = (src>=0 && src<NN) ? acc[j][l]*isd + lb[q*129+k] : -1e9f;
                lb[q*129+k] = v;
            }
        }
    }
    __syncthreads();
    for (int i=tid; i<NK*DD; i+=256){
        int r=i>>5, c=i&31;
        int src = kstart + r; src = min(max(src,0), NN-1);
        kv[r*33+c] = g_qkvg[((size_t)b*NN + src)*512 + 256 + h*DD + c];
    }
    {
        int wid = tid>>5, lane = tid&31;
        for (int rq=0; rq<4; rq++){
            int q = wid*4 + rq;
            float m = -1e30f;
            #pragma unroll
            for (int k=lane; k<NK; k+=32) m = fmaxf(m, lb[q*129+k]);
            #pragma unroll
            for (int o=16;o;o>>=1) m = fmaxf(m, __shfl_xor_sync(0xffffffffu, m, o));
            float ssum = 0.f;
            #pragma unroll
            for (int k=lane; k<NK; k+=32){
                float e = __expf(lb[q*129+k] - m);
                lb[q*129+k] = e; ssum += e;
            }
            #pragma unroll
            for (int o=16;o;o>>=1) ssum += __shfl_xor_sync(0xffffffffu, ssum, o);
            float invs = 1.f/ssum;
            #pragma unroll
            for (int k=lane; k<NK; k+=32) lb[q*129+k] *= invs;
        }
    }
    __syncthreads();
    {
        int qp = tid>>4, dp = tid&15;
        float av[2][2] = {};
        #pragma unroll 4
        for (int k=0;k<NK;k++){
            float p0 = lb[(qp*2  )*129 + k];
            float p1 = lb[(qp*2+1)*129 + k];
            float v0 = kv[k*33 + dp];
            float v1 = kv[k*33 + dp + 16];
            av[0][0]+=p0*v0; av[0][1]+=p0*v1; av[1][0]+=p1*v0; av[1][1]+=p1*v1;
        }
        #pragma unroll
        for (int a2=0;a2<2;a2++){
            #pragma unroll
            for (int b2=0;b2<2;b2++){
                int q = qp*2+a2, d = dp+16*b2;
                float gate = g_qkvg[(tokbase+q)*512 + 384 + h*DD + d];
                float v = gate*av[a2][b2];
                size_t off = (tokbase+q)*CA + h*DD + d;
                ushort_t hh,ll;
                split1(v,hh,ll);
                g_attH[off]=hh; g_attL[off]=ll;
            }
        }
    }
}

// ---------------- host launcher ----------------
extern "C" void kernel_launch(void* const* d_in, const int* in_sizes, int n_in,
                              void* d_out, int out_size){
    const float* q_in   = (const float*)d_in[0];
    const float* s_in   = (const float*)d_in[1];
    const float* p_in   = (const float*)d_in[2];
    const float* adaln_scale_w = (const float*)d_in[3];
    const float* adaln_scale_b = (const float*)d_in[4];
    const float* adaln_shift_w = (const float*)d_in[5];
    const float* wq = (const float*)d_in[6];
    const float* bq = (const float*)d_in[7];
    const float* wk = (const float*)d_in[8];
    const float* wv = (const float*)d_in[9];
    const float* lnz_w = (const float*)d_in[10];
    const float* lnz_b = (const float*)d_in[11];
    const float* wb_pair = (const float*)d_in[12];
    const float* wg = (const float*)d_in[13];
    const float* wo = (const float*)d_in[14];
    const float* sgate_w = (const float*)d_in[15];
    const float* sgate_b = (const float*)d_in[16];
    const float* t_scale_w = (const float*)d_in[17];
    const float* t_scale_b = (const float*)d_in[18];
    const float* t_shift_w = (const float*)d_in[19];
    const float* t_wa = (const float*)d_in[20];
    const float* t_wb = (const float*)d_in[21];
    const float* t_wo = (const float*)d_in[22];
    const float* t_sgate_w = (const float*)d_in[23];
    const float* t_sgate_b = (const float*)d_in[24];
    float* out = (float*)d_out;

    ushort_t *p_slnH,*p_slnL,*p_alnH,*p_alnL,*p_tlnH,*p_tlnL,*p_attH,*p_attL;
    ushort_t *p_wgateP,*p_wqkvgP,*p_whidP,*p_wwoP,*p_wtwoP;
    float *p_gatesP,*p_qkvg,*p_ao,*p_a,*p_hid,*p_bgate,*p_bqkvg;
    cudaGetSymbolAddress((void**)&p_slnH, g_slnH);
    cudaGetSymbolAddress((void**)&p_slnL, g_slnL);
    cudaGetSymbolAddress((void**)&p_alnH, g_alnH);
    cudaGetSymbolAddress((void**)&p_alnL, g_alnL);
    cudaGetSymbolAddress((void**)&p_tlnH, g_tlnH);
    cudaGetSymbolAddress((void**)&p_tlnL, g_tlnL);
    cudaGetSymbolAddress((void**)&p_attH, g_attH);
    cudaGetSymbolAddress((void**)&p_attL, g_attL);
    cudaGetSymbolAddress((void**)&p_wgateP, g_wgateP);
    cudaGetSymbolAddress((void**)&p_wqkvgP, g_wqkvgP);
    cudaGetSymbolAddress((void**)&p_whidP,  g_whidP);
    cudaGetSymbolAddress((void**)&p_wwoP,   g_wwoP);
    cudaGetSymbolAddress((void**)&p_wtwoP,  g_wtwoP);
    cudaGetSymbolAddress((void**)&p_gatesP, g_gatesP);
    cudaGetSymbolAddress((void**)&p_qkvg,   g_qkvg);
    cudaGetSymbolAddress((void**)&p_ao,     g_ao);
    cudaGetSymbolAddress((void**)&p_a,      g_a);
    cudaGetSymbolAddress((void**)&p_hid,    g_hid);
    cudaGetSymbolAddress((void**)&p_bgate,  g_bgate);
    cudaGetSymbolAddress((void**)&p_bqkvg,  g_bqkvg);

    cudaFuncSetAttribute(gemm_kernel<false>, cudaFuncAttributeMaxDynamicSharedMemorySize, GEMM_SMEM);
    cudaFuncSetAttribute(gemm_kernel<true>,  cudaFuncAttributeMaxDynamicSharedMemorySize, GEMM_SMEM);

    const ushort_t* U0 = (const ushort_t*)0;
    const float*    F0 = (const float*)0;
    // stage 0
    {
        int total = CS*NG + 2*NB*128*512 + NB*128*128 + NB*256*128 + NG + NB*512;
        pack_kernel<<<(total+255)/256,256>>>(adaln_scale_w, adaln_shift_w, sgate_w,
            t_scale_w, t_shift_w, t_sgate_w,
            adaln_scale_b, sgate_b, t_scale_b, t_sgate_b,
            wq, bq, wk, wv, wg, t_wa, t_wb, wo, t_wo);
    }
    sln_kernel<<<TT,128>>>(s_in);
    bias_kernel<<<ROWS/256,256>>>(p_in, lnz_w, lnz_b, wb_pair);
    gemm_kernel<false><<<dim3(NG/128, TT/64),256,GEMM_SMEM>>>(
        p_slnH, p_slnL, CS, F0, F0, 0,
        p_wgateP, p_bgate, (0x2Du)|(0x2Du<<6)|(0x2Du<<12),
        F0, 0, F0, 0, p_gatesP, TT, NG, CS,
        U0, U0, U0, F0, 0u, (float*)0, 1<<30);

    // stage 1
    const float* acur = q_in;
    for (int i=0;i<NB;i++){
        lnmod_kernel<<<TT,128>>>(acur, i);
        // fused qkvg (bx<4) + hid (bx>=4), both [TT,512], K=128
        gemm_kernel<false><<<dim3(8, TT/64),256,GEMM_SMEM>>>(
            p_alnH, p_alnL, CA, F0, F0, 0,
            p_wqkvgP + (size_t)i*2*128*512, p_bqkvg + i*512, 8u,
            F0, 0, F0, 0, p_qkvg, TT, 512, CA,
            p_tlnH, p_tlnL, p_whidP + (size_t)i*2*128*512, F0, 0u, p_hid, 4);
        attn_kernel<<<dim3(WW,HH,Bb),256>>>(i);
        gemm_kernel<false><<<dim3(1, TT/64),256,GEMM_SMEM>>>(
            p_attH, p_attL, CA, F0, F0, 0,
            p_wwoP + (size_t)i*2*128*128, F0, 0u,
            p_gatesP + (size_t)(i*6+2)*128, NG, F0, 0, p_ao, TT, CA, CA,
            U0, U0, U0, F0, 0u, (float*)0, 1<<30);
        gemm_kernel<false><<<dim3(4, TT/64),256,GEMM_SMEM>>>(
            p_tlnH, p_tlnL, CA, F0, F0, 0,
            p_whidP + (size_t)i*2*128*512, F0, 0u,
            F0, 0, F0, 0, p_hid, TT, 512, CA,
            U0, U0, U0, F0, 0u, (float*)0, 1<<30);
        float* dst = (i==NB-1) ? out : p_a;
        gemm_kernel<true><<<dim3(1, TT/64),256,GEMM_SMEM>>>(
            U0, U0, 0, p_hid, p_hid + 256, 512,
            p_wtwoP + (size_t)i*2*256*128, F0, 0u,
            p_gatesP + (size_t)(i*6+5)*128, NG, p_ao, CA, dst, TT, CA, HID,
            U0, U0, U0, F0, 0u, (float*)0, 1<<30);
        acur = p_a;
    }
    (void)in_sizes; (void)n_in; (void)out_size;
}

// round 16
// speedup vs baseline: 1.0685x; 1.0685x over previous
#include <cuda_runtime.h>
#include <cuda_bf16.h>
#include <math.h>

#define Bb  2
#define NN  8192
#define CA  128
#define CS  384
#define CZ  16
#define HH  4
#define DD  32
#define NQ  32
#define NK  128
#define NB  3
#define WW  256
#define HID 256
#define TT  (Bb*NN)
#define ROWS 2097152
#define NG  2304

typedef unsigned short ushort_t;

// ---------------- scratch ----------------
__device__ ushort_t g_slnH[(size_t)TT*CS], g_slnL[(size_t)TT*CS];
__device__ float    g_gatesP[(size_t)TT*NG];
__device__ float    g_biasbuf[(size_t)NB*HH*ROWS];
__device__ ushort_t g_alnH[(size_t)TT*CA], g_alnL[(size_t)TT*CA];
__device__ ushort_t g_tlnH[(size_t)TT*CA], g_tlnL[(size_t)TT*CA];
__device__ float    g_qkvg[(size_t)TT*512];
__device__ ushort_t g_attH[(size_t)TT*CA], g_attL[(size_t)TT*CA];
__device__ float    g_ao [(size_t)TT*CA];
__device__ float    g_a  [(size_t)TT*CA];
__device__ float    g_hid[(size_t)TT*512];
// pre-split weights: [plane][k][n] bf16
__device__ ushort_t g_wgateP[(size_t)2*CS*NG];
__device__ ushort_t g_wqkvgP[(size_t)NB*2*128*512];
__device__ ushort_t g_whidP [(size_t)NB*2*128*512];
__device__ ushort_t g_wwoP  [(size_t)NB*2*128*128];
__device__ ushort_t g_wtwoP [(size_t)NB*2*256*128];
__device__ float    g_bgate[NG];
__device__ float    g_bqkvg[NB*512];

__device__ __forceinline__ float sigm(float x){ return 1.f/(1.f+__expf(-x)); }

__device__ __forceinline__ void split1(float x, ushort_t &hi, ushort_t &lo){
    __nv_bfloat16 h = __float2bfloat16(x);
    hi = __bfloat16_as_ushort(h);
    lo = __bfloat16_as_ushort(__float2bfloat16(x - __bfloat162float(h)));
}
__device__ __forceinline__ void split2(float x0, float x1, unsigned &hi, unsigned &lo){
    ushort_t h0,l0,h1,l1;
    split1(x0,h0,l0); split1(x1,h1,l1);
    hi = (unsigned)h0 | ((unsigned)h1<<16);
    lo = (unsigned)l0 | ((unsigned)l1<<16);
}

__device__ __forceinline__ void mma_bf16(float* c, const unsigned* a, const unsigned* b){
    asm volatile(
        "mma.sync.aligned.m16n8k16.row.col.f32.bf16.bf16.f32 "
        "{%0,%1,%2,%3},{%4,%5,%6,%7},{%8,%9},{%0,%1,%2,%3};"
        : "+f"(c[0]), "+f"(c[1]), "+f"(c[2]), "+f"(c[3])
        : "r"(a[0]), "r"(a[1]), "r"(a[2]), "r"(a[3]), "r"(b[0]), "r"(b[1]));
}
__device__ __forceinline__ void ldsm_x4(unsigned* r, unsigned addr){
    asm volatile("ldmatrix.sync.aligned.m8n8.x4.shared.b16 {%0,%1,%2,%3}, [%4];"
        : "=r"(r[0]),"=r"(r[1]),"=r"(r[2]),"=r"(r[3]) : "r"(addr));
}
__device__ __forceinline__ void ldsm_x4_t(unsigned* r, unsigned addr){
    asm volatile("ldmatrix.sync.aligned.m8n8.x4.trans.shared.b16 {%0,%1,%2,%3}, [%4];"
        : "=r"(r[0]),"=r"(r[1]),"=r"(r[2]),"=r"(r[3]) : "r"(addr));
}
__device__ __forceinline__ void cp16(unsigned saddr, const void* gaddr){
    asm volatile("cp.async.cg.shared.global [%0], [%1], 16;" :: "r"(saddr), "l"(gaddr));
}
#define CP_COMMIT() asm volatile("cp.async.commit_group;")
#define CP_WAIT0()  asm volatile("cp.async.wait_group 0;")

__device__ __forceinline__ void blockReduce2_128(float& s, float& q){
    __shared__ float sb[8];
    #pragma unroll
    for (int o=16;o;o>>=1){
        s += __shfl_xor_sync(0xffffffffu, s, o);
        q += __shfl_xor_sync(0xffffffffu, q, o);
    }
    int wid = threadIdx.x>>5;
    if ((threadIdx.x&31)==0){ sb[wid*2]=s; sb[wid*2+1]=q; }
    __syncthreads();
    s = sb[0]+sb[2]+sb[4]+sb[6];
    q = sb[1]+sb[3]+sb[5]+sb[7];
}

// ---------------- weight packing (layout [plane][k][n]) ----------------
__global__ void pack_kernel(
    const float* __restrict__ aw,  const float* __restrict__ ashw,
    const float* __restrict__ sgw, const float* __restrict__ tsw,
    const float* __restrict__ tshw,const float* __restrict__ tsgw,
    const float* __restrict__ a_sb,const float* __restrict__ sg_b,
    const float* __restrict__ ts_b,const float* __restrict__ tsg_b,
    const float* __restrict__ wq,  const float* __restrict__ bq,
    const float* __restrict__ wk,  const float* __restrict__ wv,
    const float* __restrict__ wg,  const float* __restrict__ twa,
    const float* __restrict__ twb, const float* __restrict__ wo,
    const float* __restrict__ two)
{
    int idx = blockIdx.x*256 + threadIdx.x;
    const int R1 = CS*NG;
    const int R2 = NB*128*512;
    const int R3 = NB*128*512;
    const int R4 = NB*128*128;
    const int R5 = NB*256*128;
    ushort_t h,l;
    if (idx < R1){
        int k = idx / NG, r = idx % NG;
        int gi = r>>7, c = r&127;
        int i = gi/6, g = gi - i*6;
        const float* src;
        switch(g){
            case 0: src=aw; break; case 1: src=ashw; break; case 2: src=sgw; break;
            case 3: src=tsw; break; case 4: src=tshw; break; default: src=tsgw; break;
        }
        split1(src[((size_t)i*CS + k)*CA + c], h, l);
        g_wgateP[idx] = h; g_wgateP[(size_t)CS*NG + idx] = l;
        return;
    }
    idx -= R1;
    if (idx < R2){
        int blk = idx/(128*512), r = idx%(128*512);
        int k = r>>9, j = r&511;
        float v;
        if (j < 128)      v = wq[((size_t)blk*CA + k)*128 + j];
        else if (j < 256) v = wk[((size_t)blk*CA + k)*128 + (j-128)];
        else if (j < 384) v = wv[((size_t)blk*CA + k)*128 + (j-256)];
        else              v = wg[((size_t)blk*CA + k)*128 + (j-384)];
        split1(v,h,l);
        size_t base = (size_t)blk*2*128*512;
        g_wqkvgP[base + r] = h; g_wqkvgP[base + 128*512 + r] = l;
        return;
    }
    idx -= R2;
    if (idx < R3){
        int blk = idx/(128*512), r = idx%(128*512);
        int k = r>>9, j = r&511;
        float v = (j<256) ? twa[((size_t)blk*CA + k)*256 + j]
                          : twb[((size_t)blk*CA + k)*256 + (j-256)];
        split1(v,h,l);
        size_t base = (size_t)blk*2*128*512;
        g_whidP[base + r] = h; g_whidP[base + 128*512 + r] = l;
        return;
    }
    idx -= R3;
    if (idx < R4){
        int blk = idx/(128*128), r = idx%(128*128);
        int k = r>>7, n = r&127;
        split1(wo[(size_t)blk*CA*CA + (size_t)k*CA + n], h, l);
        size_t base = (size_t)blk*2*128*128;
        g_wwoP[base + r] = h; g_wwoP[base + 128*128 + r] = l;
        return;
    }
    idx -= R4;
    if (idx < R5){
        int blk = idx/(256*128), r = idx%(256*128);
        int k = r>>7, n = r&127;
        split1(two[(size_t)blk*HID*CA + (size_t)k*CA + n], h, l);
        size_t base = (size_t)blk*2*256*128;
        g_wtwoP[base + r] = h; g_wtwoP[base + 256*128 + r] = l;
        return;
    }
    idx -= R5;
    if (idx < NG){
        int gi = idx>>7, c = idx&127;
        int i = gi/6, g = gi - i*6;
        float v = 0.f;
        if (g==0) v = a_sb[i*128+c];
        else if (g==2) v = sg_b[i*128+c];
        else if (g==3) v = ts_b[i*128+c];
        else if (g==5) v = tsg_b[i*128+c];
        g_bgate[idx] = v;
        return;
    }
    idx -= NG;
    if (idx < NB*512){
        int blk = idx>>9, j = idx&511;
        g_bqkvg[idx] = (j<128) ? bq[blk*128 + j] : 0.f;
    }
}

// ---------------- K1: layernorm of s ----------------
__global__ void sln_kernel(const float* __restrict__ s){
    int t = blockIdx.x, tid = threadIdx.x;
    const float* row = s + (size_t)t*CS;
    float v0=row[tid], v1=row[tid+128], v2=row[tid+256];
    float su=v0+v1+v2, sq=v0*v0+v1*v1+v2*v2;
    blockReduce2_128(su,sq);
    float mean = su*(1.f/CS);
    float var  = sq*(1.f/CS) - mean*mean;
    float inv  = rsqrtf(var + 1e-5f);
    size_t base = (size_t)t*CS;
    ushort_t h,l;
    split1((v0-mean)*inv,h,l); g_slnH[base+tid]=h;     g_slnL[base+tid]=l;
    split1((v1-mean)*inv,h,l); g_slnH[base+tid+128]=h; g_slnL[base+tid+128]=l;
    split1((v2-mean)*inv,h,l); g_slnH[base+tid+256]=h; g_slnL[base+tid+256]=l;
}

// ---------------- K3: pair bias ----------------
__global__ void bias_kernel(const float* __restrict__ p, const float* __restrict__ lnz_w,
                            const float* __restrict__ lnz_b, const float* __restrict__ wb){
    __shared__ float s_w[NB*CZ], s_b[NB*CZ], s_wb[NB*CZ*HH];
    int tid = threadIdx.x;
    if (tid < NB*CZ){ s_w[tid]=lnz_w[tid]; s_b[tid]=lnz_b[tid]; }
    if (tid < NB*CZ*HH) s_wb[tid]=wb[tid];
    __syncthreads();
    size_t r = (size_t)blockIdx.x*blockDim.x + tid;
    if (r >= (size_t)ROWS) return;
    const float4* p4 = (const float4*)(p + r*CZ);
    float z[16];
    float4 q0=p4[0], q1=p4[1], q2=p4[2], q3=p4[3];
    z[0]=q0.x; z[1]=q0.y; z[2]=q0.z; z[3]=q0.w;
    z[4]=q1.x; z[5]=q1.y; z[6]=q1.z; z[7]=q1.w;
    z[8]=q2.x; z[9]=q2.y; z[10]=q2.z; z[11]=q2.w;
    z[12]=q3.x; z[13]=q3.y; z[14]=q3.z; z[15]=q3.w;
    float su=0, sq=0;
    #pragma unroll
    for (int c=0;c<16;c++){ su+=z[c]; sq+=z[c]*z[c]; }
    float mean=su*(1.f/16.f), var=sq*(1.f/16.f)-mean*mean;
    float inv=rsqrtf(var+1e-5f);
    #pragma unroll
    for (int c=0;c<16;c++) z[c]=(z[c]-mean)*inv;
    #pragma unroll
    for (int i=0;i<NB;i++){
        float o0=0,o1=0,o2=0,o3=0;
        #pragma unroll
        for (int c=0;c<16;c++){
            float zz = z[c]*s_w[i*16+c] + s_b[i*16+c];
            const float* w4 = &s_wb[(i*16+c)*4];
            o0 += zz*w4[0]; o1 += zz*w4[1]; o2 += zz*w4[2]; o3 += zz*w4[3];
        }
        size_t base = ((size_t)i*HH)*ROWS + r;
        g_biasbuf[base]        = o0;
        g_biasbuf[base+ROWS]   = o1;
        g_biasbuf[base+2*(size_t)ROWS] = o2;
        g_biasbuf[base+3*(size_t)ROWS] = o3;
    }
}

// ---------------- K4: LN(a) + modulations ----------------
__global__ void lnmod_kernel(const float* __restrict__ a, int blk){
    int t = blockIdx.x, c = threadIdx.x;
    float x = a[(size_t)t*CA + c];
    float su=x, sq=x*x;
    blockReduce2_128(su,sq);
    float mean=su*(1.f/CA), var=sq*(1.f/CA)-mean*mean;
    float xn=(x-mean)*rsqrtf(var+1e-5f);
    size_t base = (size_t)t*NG;
    float sc  = g_gatesP[base + (blk*6+0)*128 + c];
    float sh_ = g_gatesP[base + (blk*6+1)*128 + c];
    float tsc = g_gatesP[base + (blk*6+3)*128 + c];
    float tsh = g_gatesP[base + (blk*6+4)*128 + c];
    size_t o=(size_t)t*CA+c;
    ushort_t h,l;
    split1(sc*xn + sh_, h, l); g_alnH[o]=h; g_alnL[o]=l;
    split1(tsc*xn + tsh, h, l); g_tlnH[o]=h; g_tlnL[o]=l;
}

// ---------------- GEMM: 3xBF16 m16n8k16 + ldmatrix + cp.async, BK=32, 2-stage, BM=64 ----------------
// Optional second task: CTAs with blockIdx.x >= nsplit use (AH2/AL2, BP2, biasv2, sigmask2, C2).
#define AS_  40
#define BSr  136
#define APL (64*AS_)
#define BPL (32*BSr)
#define BUFH (2*APL + 2*BPL)
#define NSTG 2
#define GEMM_SMEM (NSTG*BUFH*2)
template<bool GLU>
__global__ void __launch_bounds__(256, GLU?2:3) gemm_kernel(
        const ushort_t* __restrict__ AHp, const ushort_t* __restrict__ ALp, int lda,
        const float* __restrict__ Af, const float* __restrict__ A2f, int ldaf,
        const ushort_t* __restrict__ BPp,
        const float* __restrict__ biasvp, unsigned sigmaskp,
        const float* __restrict__ mulp, int ldmul,
        const float* __restrict__ addp, int ldadd,
        float* __restrict__ Cp, int M, int N, int K,
        const ushort_t* AH2, const ushort_t* AL2, const ushort_t* BP2,
        const float* biasv2, unsigned sigmask2, float* C2, int nsplit){
    extern __shared__ __align__(16) ushort_t sh[];
    const ushort_t* AH = AHp; const ushort_t* AL = ALp; const ushort_t* BP = BPp;
    const float* biasv = biasvp; unsigned sigmask = sigmaskp; float* C = Cp;
    int bx = blockIdx.x;
    if (AH2 && bx >= nsplit){
        AH = AH2; AL = AL2; BP = BP2; biasv = biasv2; sigmask = sigmask2; C = C2;
        bx -= nsplit;
    }
    int n0 = bx*128, m0 = blockIdx.y*64;
    int tid = threadIdx.x, lane = tid&31, wid = tid>>5;
    int g = lane>>2, tig = lane&3;
    int wm = (wid&1)*32, wn = (wid>>1)*32;
    float acc[2][4][4] = {};
    const int nit = K>>5;
    unsigned sbase = (unsigned)__cvta_generic_to_shared(sh);

    // A cp.async mapping (non-GLU)
    int apl_ = tid>>7, ac = tid&127;
    int arow1 = ac>>2, aq = ac&3;
    int arow2 = arow1 + 32;
    const ushort_t* AsrcP = 0;
    unsigned adst1 = 0, adst2 = 0;
    // A register path (GLU)
    int ar = tid>>2, akq = tid&3;
    const float *Apf = 0, *Gpf = 0;
    if (GLU){
        Apf = Af + (size_t)(m0+ar)*ldaf;
        Gpf = A2f + (size_t)(m0+ar)*ldaf;
    } else {
        AsrcP = (apl_ ? AL : AH) + (size_t)m0*lda;
        adst1 = (unsigned)((apl_*APL + arow1*AS_ + aq*8)*2);
        adst2 = (unsigned)((apl_*APL + arow2*AS_ + aq*8)*2);
    }
    // B cp.async mapping
    int bpl = tid>>7, bcid = tid&127;
    int brow = bcid>>4, bseg = (bcid&15)*8;
    const ushort_t* BsrcP = BP + (size_t)bpl*K*N + n0 + bseg;
    unsigned bdstb = (unsigned)((2*APL + bpl*BPL + bseg)*2);

    auto issue_tile = [&](int it){
        unsigned nb = (unsigned)((it&1)*BUFH*2);
        int kb = it*32;
        if (!GLU){
            cp16(sbase + nb + adst1, AsrcP + (size_t)(arow1)*lda + kb + aq*8);
            cp16(sbase + nb + adst2, AsrcP + (size_t)(arow2)*lda + kb + aq*8);
        }
        #pragma unroll
        for (int rr=0; rr<4; rr++){
            int kr = brow + rr*8;
            cp16(sbase + nb + bdstb + (unsigned)(kr*BSr*2),
                 BsrcP + (size_t)(kb + kr)*N);
        }
        CP_COMMIT();
    };
    auto store_A_glu = [&](int it){
        ushort_t* base = sh + (it&1)*BUFH;
        #pragma unroll
        for (int q=0; q<2; q++){
            int koff = it*32 + akq*4 + q*16;
            float4 v  = *(const float4*)(Apf + koff);
            float4 gv = *(const float4*)(Gpf + koff);
            v.x = v.x*sigm(v.x)*gv.x; v.y = v.y*sigm(v.y)*gv.y;
            v.z = v.z*sigm(v.z)*gv.z; v.w = v.w*sigm(v.w)*gv.w;
            unsigned h01,l01,h23,l23;
            split2(v.x,v.y,h01,l01);
            split2(v.z,v.w,h23,l23);
            int so = ar*AS_ + akq*4 + q*16;
            *(unsigned*)(base + so)           = h01;
            *(unsigned*)(base + so + 2)       = h23;
            *(unsigned*)(base + APL + so)     = l01;
            *(unsigned*)(base + APL + so + 2) = l23;
        }
    };

    // prologue
    issue_tile(0); if (GLU) store_A_glu(0);
    CP_WAIT0();
    __syncthreads();

    // ldmatrix per-thread byte offsets
    int mi = lane>>3, r8 = lane&7;
    unsigned aoff0 = (unsigned)(((wm + (mi&1)*8 + r8)*AS_ + (mi>>1)*8)*2);
    unsigned aoff1 = aoff0 + (unsigned)(16*AS_*2);
    unsigned boff0 = (unsigned)((((mi&1)*8 + r8)*BSr + wn + (mi>>1)*8)*2);
    unsigned boff1 = boff0 + 32;

    for (int it=0; it<nit; it++){
        if (it+1 < nit){
            issue_tile(it+1);
            if (GLU) store_A_glu(it+1);
        }
        unsigned bufb = sbase + (unsigned)((it&1)*BUFH*2);
        #pragma unroll
        for (int ks=0; ks<2; ks++){
            unsigned ka = bufb + (unsigned)(ks*32);
            unsigned kb = bufb + (unsigned)(ks*16*BSr*2);
            unsigned ah[2][4], alo[2][4], bh[2][4], bl[2][4];
            ldsm_x4(ah[0],  ka + aoff0);
            ldsm_x4(ah[1],  ka + aoff1);
            ldsm_x4(alo[0], ka + (unsigned)(APL*2) + aoff0);
            ldsm_x4(alo[1], ka + (unsigned)(APL*2) + aoff1);
            ldsm_x4_t(bh[0], kb + (unsigned)(2*APL*2) + boff0);
            ldsm_x4_t(bh[1], kb + (unsigned)(2*APL*2) + boff1);
            ldsm_x4_t(bl[0], kb + (unsigned)((2*APL+BPL)*2) + boff0);
            ldsm_x4_t(bl[1], kb + (unsigned)((2*APL+BPL)*2) + boff1);
            #pragma unroll
            for (int mt=0; mt<2; mt++){
                #pragma unroll
                for (int nt=0; nt<4; nt++){
                    const unsigned* bph = &bh[nt>>1][(nt&1)*2];
                    const unsigned* bpl_ = &bl[nt>>1][(nt&1)*2];
                    mma_bf16(acc[mt][nt], ah[mt],  bph);
                    mma_bf16(acc[mt][nt], ah[mt],  bpl_);
                    mma_bf16(acc[mt][nt], alo[mt], bph);
                }
            }
        }
        if (it+1 < nit) CP_WAIT0();
        __syncthreads();
    }

    // epilogue
    #pragma unroll
    for (int mt=0; mt<2; mt++){
        #pragma unroll
        for (int nt=0; nt<4; nt++){
            int row0 = m0 + wm + mt*16 + g;
            int row1 = row0 + 8;
            int col  = n0 + wn + nt*8 + 2*tig;
            float b0 = biasv ? biasv[col]   : 0.f;
            float b1 = biasv ? biasv[col+1] : 0.f;
            float e0 = acc[mt][nt][0] + b0, e1 = acc[mt][nt][1] + b1;
            float e2 = acc[mt][nt][2] + b0, e3 = acc[mt][nt][3] + b1;
            if ((sigmask >> (col>>7)) & 1u){ e0=sigm(e0); e1=sigm(e1); e2=sigm(e2); e3=sigm(e3); }
            size_t o0 = (size_t)row0*N + col, o1 = (size_t)row1*N + col;
            if (mulp){
                size_t u0 = (size_t)row0*ldmul + col, u1 = (size_t)row1*ldmul + col;
                e0*=mulp[u0]; e1*=mulp[u0+1]; e2*=mulp[u1]; e3*=mulp[u1+1];
            }
            if (addp){
                size_t u0 = (size_t)row0*ldadd + col, u1 = (size_t)row1*ldadd + col;
                e0+=addp[u0]; e1+=addp[u0+1]; e2+=addp[u1]; e3+=addp[u1+1];
            }
            *(float2*)&C[o0] = make_float2(e0,e1);
            *(float2*)&C[o1] = make_float2(e2,e3);
        }
    }
}

// ---------------- K6: windowed attention ----------------
__global__ void attn_kernel(int blk){
    __shared__ float qs[NQ*DD];
    __shared__ float kv[NK*33];
    __shared__ float lb[NQ*129];
    int w = blockIdx.x, h = blockIdx.y, b = blockIdx.z;
    int tid = threadIdx.x;
    size_t tokbase = (size_t)b*NN + (size_t)w*NQ;
    int kstart = w*NQ - 48;
    for (int i=tid; i<NQ*DD; i+=256){
        int r=i>>5, c=i&31;
        qs[i] = g_qkvg[(tokbase+r)*512 + h*DD + c];
    }
    for (int i=tid; i<NK*DD; i+=256){
        int r=i>>5, c=i&31;
        int src = kstart + r; src = min(max(src,0), NN-1);
        kv[r*33+c] = g_qkvg[((size_t)b*NN + src)*512 + 128 + h*DD + c];
    }
    const float* plane = g_biasbuf + ((size_t)blk*HH + h)*(size_t)ROWS;
    size_t rb = (((size_t)b*WW + w)*NQ)*NK;
    for (int i=tid; i<NQ*NK; i+=256){
        int q=i>>7, k=i&127;
        lb[q*129+k] = plane[rb + i];
    }
    __syncthreads();
    {
        int qt = tid>>5, kt = tid&31;
        float acc[4][4] = {};
        #pragma unroll
        for (int d=0; d<DD; d++){
            float qa[4], kb[4];
            #pragma unroll
            for (int j=0;j<4;j++) qa[j] = qs[(qt*4+j)*DD + d];
            #pragma unroll
            for (int l=0;l<4;l++) kb[l] = kv[(kt+32*l)*33 + d];
            #pragma unroll
            for (int j=0;j<4;j++)
                #pragma unroll
                for (int l=0;l<4;l++) acc[j][l] += qa[j]*kb[l];
        }
        const float isd = 0.17677669529663687f;
        #pragma unroll
        for (int j=0;j<4;j++){
            #pragma unroll
            for (int l=0;l<4;l++){
                int q = qt*4+j, k = kt+32*l;
                int src = kstart + k;
                float v = (src>=0 && src<NN) ? acc[j][l]*isd + lb[q*129+k] : -1e9f;
                lb[q*129+k] = v;
            }
        }
    }
    __syncthreads();
    for (int i=tid; i<NK*DD; i+=256){
        int r=i>>5, c=i&31;
        int src = kstart + r; src = min(max(src,0), NN-1);
        kv[r*33+c] = g_qkvg[((size_t)b*NN + src)*512 + 256 + h*DD + c];
    }
    {
        int wid = tid>>5, lane = tid&31;
        for (int rq=0; rq<4; rq++){
            int q = wid*4 + rq;
            float m = -1e30f;
            #pragma unroll
            for (int k=lane; k<NK; k+=32) m = fmaxf(m, lb[q*129+k]);
            #pragma unroll
            for (int o=16;o;o>>=1) m = fmaxf(m, __shfl_xor_sync(0xffffffffu, m, o));
            float ssum = 0.f;
            #pragma unroll
            for (int k=lane; k<NK; k+=32){
                float e = __expf(lb[q*129+k] - m);
                lb[q*129+k] = e; ssum += e;
            }
            #pragma unroll
            for (int o=16;o;o>>=1) ssum += __shfl_xor_sync(0xffffffffu, ssum, o);
            float invs = 1.f/ssum;
            #pragma unroll
            for (int k=lane; k<NK; k+=32) lb[q*129+k] *= invs;
        }
    }
    __syncthreads();
    {
        int qp = tid>>4, dp = tid&15;
        float av[2][2] = {};
        #pragma unroll 4
        for (int k=0;k<NK;k++){
            float p0 = lb[(qp*2  )*129 + k];
            float p1 = lb[(qp*2+1)*129 + k];
            float v0 = kv[k*33 + dp];
            float v1 = kv[k*33 + dp + 16];
            av[0][0]+=p0*v0; av[0][1]+=p0*v1; av[1][0]+=p1*v0; av[1][1]+=p1*v1;
        }
        #pragma unroll
        for (int a2=0;a2<2;a2++){
            #pragma unroll
            for (int b2=0;b2<2;b2++){
                int q = qp*2+a2, d = dp+16*b2;
                float gate = g_qkvg[(tokbase+q)*512 + 384 + h*DD + d];
                float v = gate*av[a2][b2];
                size_t off = (tokbase+q)*CA + h*DD + d;
                ushort_t hh,ll;
                split1(v,hh,ll);
                g_attH[off]=hh; g_attL[off]=ll;
            }
        }
    }
}

// ---------------- host launcher ----------------
extern "C" void kernel_launch(void* const* d_in, const int* in_sizes, int n_in,
                              void* d_out, int out_size){
    const float* q_in   = (const float*)d_in[0];
    const float* s_in   = (const float*)d_in[1];
    const float* p_in   = (const float*)d_in[2];
    const float* adaln_scale_w = (const float*)d_in[3];
    const float* adaln_scale_b = (const float*)d_in[4];
    const float* adaln_shift_w = (const float*)d_in[5];
    const float* wq = (const float*)d_in[6];
    const float* bq = (const float*)d_in[7];
    const float* wk = (const float*)d_in[8];
    const float* wv = (const float*)d_in[9];
    const float* lnz_w = (const float*)d_in[10];
    const float* lnz_b = (const float*)d_in[11];
    const float* wb_pair = (const float*)d_in[12];
    const float* wg = (const float*)d_in[13];
    const float* wo = (const float*)d_in[14];
    const float* sgate_w = (const float*)d_in[15];
    const float* sgate_b = (const float*)d_in[16];
    const float* t_scale_w = (const float*)d_in[17];
    const float* t_scale_b = (const float*)d_in[18];
    const float* t_shift_w = (const float*)d_in[19];
    const float* t_wa = (const float*)d_in[20];
    const float* t_wb = (const float*)d_in[21];
    const float* t_wo = (const float*)d_in[22];
    const float* t_sgate_w = (const float*)d_in[23];
    const float* t_sgate_b = (const float*)d_in[24];
    float* out = (float*)d_out;

    ushort_t *p_slnH,*p_slnL,*p_alnH,*p_alnL,*p_tlnH,*p_tlnL,*p_attH,*p_attL;
    ushort_t *p_wgateP,*p_wqkvgP,*p_whidP,*p_wwoP,*p_wtwoP;
    float *p_gatesP,*p_qkvg,*p_ao,*p_a,*p_hid,*p_bgate,*p_bqkvg;
    cudaGetSymbolAddress((void**)&p_slnH, g_slnH);
    cudaGetSymbolAddress((void**)&p_slnL, g_slnL);
    cudaGetSymbolAddress((void**)&p_alnH, g_alnH);
    cudaGetSymbolAddress((void**)&p_alnL, g_alnL);
    cudaGetSymbolAddress((void**)&p_tlnH, g_tlnH);
    cudaGetSymbolAddress((void**)&p_tlnL, g_tlnL);
    cudaGetSymbolAddress((void**)&p_attH, g_attH);
    cudaGetSymbolAddress((void**)&p_attL, g_attL);
    cudaGetSymbolAddress((void**)&p_wgateP, g_wgateP);
    cudaGetSymbolAddress((void**)&p_wqkvgP, g_wqkvgP);
    cudaGetSymbolAddress((void**)&p_whidP,  g_whidP);
    cudaGetSymbolAddress((void**)&p_wwoP,   g_wwoP);
    cudaGetSymbolAddress((void**)&p_wtwoP,  g_wtwoP);
    cudaGetSymbolAddress((void**)&p_gatesP, g_gatesP);
    cudaGetSymbolAddress((void**)&p_qkvg,   g_qkvg);
    cudaGetSymbolAddress((void**)&p_ao,     g_ao);
    cudaGetSymbolAddress((void**)&p_a,      g_a);
    cudaGetSymbolAddress((void**)&p_hid,    g_hid);
    cudaGetSymbolAddress((void**)&p_bgate,  g_bgate);
    cudaGetSymbolAddress((void**)&p_bqkvg,  g_bqkvg);

    cudaFuncSetAttribute(gemm_kernel<false>, cudaFuncAttributeMaxDynamicSharedMemorySize, GEMM_SMEM);
    cudaFuncSetAttribute(gemm_kernel<true>,  cudaFuncAttributeMaxDynamicSharedMemorySize, GEMM_SMEM);

    const ushort_t* U0 = (const ushort_t*)0;
    const float*    F0 = (const float*)0;
    // stage 0
    {
        int total = CS*NG + 2*NB*128*512 + NB*128*128 + NB*256*128 + NG + NB*512;
        pack_kernel<<<(total+255)/256,256>>>(adaln_scale_w, adaln_shift_w, sgate_w,
            t_scale_w, t_shift_w, t_sgate_w,
            adaln_scale_b, sgate_b, t_scale_b, t_sgate_b,
            wq, bq, wk, wv, wg, t_wa, t_wb, wo, t_wo);
    }
    sln_kernel<<<TT,128>>>(s_in);
    bias_kernel<<<ROWS/256,256>>>(p_in, lnz_w, lnz_b, wb_pair);
    gemm_kernel<false><<<dim3(NG/128, TT/64),256,GEMM_SMEM>>>(
        p_slnH, p_slnL, CS, F0, F0, 0,
        p_wgateP, p_bgate, (0x2Du)|(0x2Du<<6)|(0x2Du<<12),
        F0, 0, F0, 0, p_gatesP, TT, NG, CS,
        U0, U0, U0, F0, 0u, (float*)0, 1<<30);

    // stage 1
    const float* acur = q_in;
    for (int i=0;i<NB;i++){
        lnmod_kernel<<<TT,128>>>(acur, i);
        // fused qkvg (bx<4) + hid (bx>=4), both [TT,512], K=128
        gemm_kernel<false><<<dim3(8, TT/64),256,GEMM_SMEM>>>(
            p_alnH, p_alnL, CA, F0, F0, 0,
            p_wqkvgP + (size_t)i*2*128*512, p_bqkvg + i*512, 8u,
            F0, 0, F0, 0, p_qkvg, TT, 512, CA,
            p_tlnH, p_tlnL, p_whidP + (size_t)i*2*128*512, F0, 0u, p_hid, 4);
        attn_kernel<<<dim3(WW,HH,Bb),256>>>(i);
        gemm_kernel<false><<<dim3(1, TT/64),256,GEMM_SMEM>>>(
            p_attH, p_attL, CA, F0, F0, 0,
            p_wwoP + (size_t)i*2*128*128, F0, 0u,
            p_gatesP + (size_t)(i*6+2)*128, NG, F0, 0, p_ao, TT, CA, CA,
            U0, U0, U0, F0, 0u, (float*)0, 1<<30);
        float* dst = (i==NB-1) ? out : p_a;
        gemm_kernel<true><<<dim3(1, TT/64),256,GEMM_SMEM>>>(
            U0, U0, 0, p_hid, p_hid + 256, 512,
            p_wtwoP + (size_t)i*2*256*128, F0, 0u,
            p_gatesP + (size_t)(i*6+5)*128, NG, p_ao, CA, dst, TT, CA, HID,
            U0, U0, U0, F0, 0u, (float*)0, 1<<30);
        acur = p_a;
    }
    (void)in_sizes; (void)n_in; (void)out_size;
}

// round 17
// speedup vs baseline: 1.0778x; 1.0087x over previous
#include <cuda_runtime.h>
#include <cuda_bf16.h>
#include <math.h>

#define Bb  2
#define NN  8192
#define CA  128
#define CS  384
#define CZ  16
#define HH  4
#define DD  32
#define NQ  32
#define NK  128
#define NB  3
#define WW  256
#define HID 256
#define TT  (Bb*NN)
#define ROWS 2097152
#define NG  2304

typedef unsigned short ushort_t;

// ---------------- scratch ----------------
__device__ ushort_t g_slnH[(size_t)TT*CS], g_slnL[(size_t)TT*CS];
__device__ float    g_gatesP[(size_t)TT*NG];
__device__ float    g_biasbuf[(size_t)NB*HH*ROWS];
__device__ ushort_t g_alnH[(size_t)TT*CA], g_alnL[(size_t)TT*CA];
__device__ ushort_t g_tlnH[(size_t)TT*CA], g_tlnL[(size_t)TT*CA];
__device__ float    g_qkvg[(size_t)TT*512];
__device__ ushort_t g_attH[(size_t)TT*CA], g_attL[(size_t)TT*CA];
__device__ float    g_ao [(size_t)TT*CA];
__device__ float    g_a  [(size_t)TT*CA];
__device__ float    g_hid[(size_t)TT*512];
// pre-split weights: [plane][k][n] bf16
__device__ ushort_t g_wgateP[(size_t)2*CS*NG];
__device__ ushort_t g_wqkvgP[(size_t)NB*2*128*512];
__device__ ushort_t g_whidP [(size_t)NB*2*128*512];
__device__ ushort_t g_wwoP  [(size_t)NB*2*128*128];
__device__ ushort_t g_wtwoP [(size_t)NB*2*256*128];
__device__ float    g_bgate[NG];
__device__ float    g_bqkvg[NB*512];

__device__ __forceinline__ float sigm(float x){ return 1.f/(1.f+__expf(-x)); }

__device__ __forceinline__ void split1(float x, ushort_t &hi, ushort_t &lo){
    __nv_bfloat16 h = __float2bfloat16(x);
    hi = __bfloat16_as_ushort(h);
    lo = __bfloat16_as_ushort(__float2bfloat16(x - __bfloat162float(h)));
}
__device__ __forceinline__ void split2(float x0, float x1, unsigned &hi, unsigned &lo){
    ushort_t h0,l0,h1,l1;
    split1(x0,h0,l0); split1(x1,h1,l1);
    hi = (unsigned)h0 | ((unsigned)h1<<16);
    lo = (unsigned)l0 | ((unsigned)l1<<16);
}

__device__ __forceinline__ void mma_bf16(float* c, const unsigned* a, const unsigned* b){
    asm volatile(
        "mma.sync.aligned.m16n8k16.row.col.f32.bf16.bf16.f32 "
        "{%0,%1,%2,%3},{%4,%5,%6,%7},{%8,%9},{%0,%1,%2,%3};"
        : "+f"(c[0]), "+f"(c[1]), "+f"(c[2]), "+f"(c[3])
        : "r"(a[0]), "r"(a[1]), "r"(a[2]), "r"(a[3]), "r"(b[0]), "r"(b[1]));
}
__device__ __forceinline__ void ldsm_x4(unsigned* r, unsigned addr){
    asm volatile("ldmatrix.sync.aligned.m8n8.x4.shared.b16 {%0,%1,%2,%3}, [%4];"
        : "=r"(r[0]),"=r"(r[1]),"=r"(r[2]),"=r"(r[3]) : "r"(addr));
}
__device__ __forceinline__ void ldsm_x4_t(unsigned* r, unsigned addr){
    asm volatile("ldmatrix.sync.aligned.m8n8.x4.trans.shared.b16 {%0,%1,%2,%3}, [%4];"
        : "=r"(r[0]),"=r"(r[1]),"=r"(r[2]),"=r"(r[3]) : "r"(addr));
}
__device__ __forceinline__ void cp16(unsigned saddr, const void* gaddr){
    asm volatile("cp.async.cg.shared.global [%0], [%1], 16;" :: "r"(saddr), "l"(gaddr));
}
#define CP_COMMIT() asm volatile("cp.async.commit_group;")
#define CP_WAIT0()  asm volatile("cp.async.wait_group 0;")

__device__ __forceinline__ void blockReduce2_128(float& s, float& q){
    __shared__ float sb[8];
    #pragma unroll
    for (int o=16;o;o>>=1){
        s += __shfl_xor_sync(0xffffffffu, s, o);
        q += __shfl_xor_sync(0xffffffffu, q, o);
    }
    int wid = threadIdx.x>>5;
    if ((threadIdx.x&31)==0){ sb[wid*2]=s; sb[wid*2+1]=q; }
    __syncthreads();
    s = sb[0]+sb[2]+sb[4]+sb[6];
    q = sb[1]+sb[3]+sb[5]+sb[7];
}

// ---------------- weight packing (layout [plane][k][n]) ----------------
__global__ void pack_kernel(
    const float* __restrict__ aw,  const float* __restrict__ ashw,
    const float* __restrict__ sgw, const float* __restrict__ tsw,
    const float* __restrict__ tshw,const float* __restrict__ tsgw,
    const float* __restrict__ a_sb,const float* __restrict__ sg_b,
    const float* __restrict__ ts_b,const float* __restrict__ tsg_b,
    const float* __restrict__ wq,  const float* __restrict__ bq,
    const float* __restrict__ wk,  const float* __restrict__ wv,
    const float* __restrict__ wg,  const float* __restrict__ twa,
    const float* __restrict__ twb, const float* __restrict__ wo,
    const float* __restrict__ two)
{
    int idx = blockIdx.x*256 + threadIdx.x;
    const int R1 = CS*NG;
    const int R2 = NB*128*512;
    const int R3 = NB*128*512;
    const int R4 = NB*128*128;
    const int R5 = NB*256*128;
    ushort_t h,l;
    if (idx < R1){
        int k = idx / NG, r = idx % NG;
        int gi = r>>7, c = r&127;
        int i = gi/6, g = gi - i*6;
        const float* src;
        switch(g){
            case 0: src=aw; break; case 1: src=ashw; break; case 2: src=sgw; break;
            case 3: src=tsw; break; case 4: src=tshw; break; default: src=tsgw; break;
        }
        split1(src[((size_t)i*CS + k)*CA + c], h, l);
        g_wgateP[idx] = h; g_wgateP[(size_t)CS*NG + idx] = l;
        return;
    }
    idx -= R1;
    if (idx < R2){
        int blk = idx/(128*512), r = idx%(128*512);
        int k = r>>9, j = r&511;
        float v;
        if (j < 128)      v = wq[((size_t)blk*CA + k)*128 + j];
        else if (j < 256) v = wk[((size_t)blk*CA + k)*128 + (j-128)];
        else if (j < 384) v = wv[((size_t)blk*CA + k)*128 + (j-256)];
        else              v = wg[((size_t)blk*CA + k)*128 + (j-384)];
        split1(v,h,l);
        size_t base = (size_t)blk*2*128*512;
        g_wqkvgP[base + r] = h; g_wqkvgP[base + 128*512 + r] = l;
        return;
    }
    idx -= R2;
    if (idx < R3){
        int blk = idx/(128*512), r = idx%(128*512);
        int k = r>>9, j = r&511;
        float v = (j<256) ? twa[((size_t)blk*CA + k)*256 + j]
                          : twb[((size_t)blk*CA + k)*256 + (j-256)];
        split1(v,h,l);
        size_t base = (size_t)blk*2*128*512;
        g_whidP[base + r] = h; g_whidP[base + 128*512 + r] = l;
        return;
    }
    idx -= R3;
    if (idx < R4){
        int blk = idx/(128*128), r = idx%(128*128);
        int k = r>>7, n = r&127;
        split1(wo[(size_t)blk*CA*CA + (size_t)k*CA + n], h, l);
        size_t base = (size_t)blk*2*128*128;
        g_wwoP[base + r] = h; g_wwoP[base + 128*128 + r] = l;
        return;
    }
    idx -= R4;
    if (idx < R5){
        int blk = idx/(256*128), r = idx%(256*128);
        int k = r>>7, n = r&127;
        split1(two[(size_t)blk*HID*CA + (size_t)k*CA + n], h, l);
        size_t base = (size_t)blk*2*256*128;
        g_wtwoP[base + r] = h; g_wtwoP[base + 256*128 + r] = l;
        return;
    }
    idx -= R5;
    if (idx < NG){
        int gi = idx>>7, c = idx&127;
        int i = gi/6, g = gi - i*6;
        float v = 0.f;
        if (g==0) v = a_sb[i*128+c];
        else if (g==2) v = sg_b[i*128+c];
        else if (g==3) v = ts_b[i*128+c];
        else if (g==5) v = tsg_b[i*128+c];
        g_bgate[idx] = v;
        return;
    }
    idx -= NG;
    if (idx < NB*512){
        int blk = idx>>9, j = idx&511;
        g_bqkvg[idx] = (j<128) ? bq[blk*128 + j] : 0.f;
    }
}

// ---------------- K1: layernorm of s ----------------
__global__ void sln_kernel(const float* __restrict__ s){
    int t = blockIdx.x, tid = threadIdx.x;
    const float* row = s + (size_t)t*CS;
    float v0=row[tid], v1=row[tid+128], v2=row[tid+256];
    float su=v0+v1+v2, sq=v0*v0+v1*v1+v2*v2;
    blockReduce2_128(su,sq);
    float mean = su*(1.f/CS);
    float var  = sq*(1.f/CS) - mean*mean;
    float inv  = rsqrtf(var + 1e-5f);
    size_t base = (size_t)t*CS;
    ushort_t h,l;
    split1((v0-mean)*inv,h,l); g_slnH[base+tid]=h;     g_slnL[base+tid]=l;
    split1((v1-mean)*inv,h,l); g_slnH[base+tid+128]=h; g_slnL[base+tid+128]=l;
    split1((v2-mean)*inv,h,l); g_slnH[base+tid+256]=h; g_slnL[base+tid+256]=l;
}

// ---------------- K3: pair bias ----------------
__global__ void bias_kernel(const float* __restrict__ p, const float* __restrict__ lnz_w,
                            const float* __restrict__ lnz_b, const float* __restrict__ wb){
    __shared__ float s_w[NB*CZ], s_b[NB*CZ], s_wb[NB*CZ*HH];
    int tid = threadIdx.x;
    if (tid < NB*CZ){ s_w[tid]=lnz_w[tid]; s_b[tid]=lnz_b[tid]; }
    if (tid < NB*CZ*HH) s_wb[tid]=wb[tid];
    __syncthreads();
    size_t r = (size_t)blockIdx.x*blockDim.x + tid;
    if (r >= (size_t)ROWS) return;
    const float4* p4 = (const float4*)(p + r*CZ);
    float z[16];
    float4 q0=p4[0], q1=p4[1], q2=p4[2], q3=p4[3];
    z[0]=q0.x; z[1]=q0.y; z[2]=q0.z; z[3]=q0.w;
    z[4]=q1.x; z[5]=q1.y; z[6]=q1.z; z[7]=q1.w;
    z[8]=q2.x; z[9]=q2.y; z[10]=q2.z; z[11]=q2.w;
    z[12]=q3.x; z[13]=q3.y; z[14]=q3.z; z[15]=q3.w;
    float su=0, sq=0;
    #pragma unroll
    for (int c=0;c<16;c++){ su+=z[c]; sq+=z[c]*z[c]; }
    float mean=su*(1.f/16.f), var=sq*(1.f/16.f)-mean*mean;
    float inv=rsqrtf(var+1e-5f);
    #pragma unroll
    for (int c=0;c<16;c++) z[c]=(z[c]-mean)*inv;
    #pragma unroll
    for (int i=0;i<NB;i++){
        float o0=0,o1=0,o2=0,o3=0;
        #pragma unroll
        for (int c=0;c<16;c++){
            float zz = z[c]*s_w[i*16+c] + s_b[i*16+c];
            const float* w4 = &s_wb[(i*16+c)*4];
            o0 += zz*w4[0]; o1 += zz*w4[1]; o2 += zz*w4[2]; o3 += zz*w4[3];
        }
        size_t base = ((size_t)i*HH)*ROWS + r;
        g_biasbuf[base]        = o0;
        g_biasbuf[base+ROWS]   = o1;
        g_biasbuf[base+2*(size_t)ROWS] = o2;
        g_biasbuf[base+3*(size_t)ROWS] = o3;
    }
}

// ---------------- K4: LN(a) + modulations ----------------
__global__ void lnmod_kernel(const float* __restrict__ a, int blk){
    int t = blockIdx.x, c = threadIdx.x;
    float x = a[(size_t)t*CA + c];
    float su=x, sq=x*x;
    blockReduce2_128(su,sq);
    float mean=su*(1.f/CA), var=sq*(1.f/CA)-mean*mean;
    float xn=(x-mean)*rsqrtf(var+1e-5f);
    size_t base = (size_t)t*NG;
    float sc  = g_gatesP[base + (blk*6+0)*128 + c];
    float sh_ = g_gatesP[base + (blk*6+1)*128 + c];
    float tsc = g_gatesP[base + (blk*6+3)*128 + c];
    float tsh = g_gatesP[base + (blk*6+4)*128 + c];
    size_t o=(size_t)t*CA+c;
    ushort_t h,l;
    split1(sc*xn + sh_, h, l); g_alnH[o]=h; g_alnL[o]=l;
    split1(tsc*xn + tsh, h, l); g_tlnH[o]=h; g_tlnL[o]=l;
}

// ---------------- GEMM: 3xBF16 m16n8k16 + ldmatrix + cp.async, BK=32, 2-stage, BM=64 ----------------
#define AS_  40
#define BSr  136
#define APL (64*AS_)
#define BPL (32*BSr)
#define BUFH (2*APL + 2*BPL)
#define NSTG 2
#define GEMM_SMEM (NSTG*BUFH*2)
template<bool GLU>
__global__ void __launch_bounds__(256, GLU?2:3) gemm_kernel(
        const ushort_t* __restrict__ AHp, const ushort_t* __restrict__ ALp, int lda,
        const float* __restrict__ Af, const float* __restrict__ A2f, int ldaf,
        const ushort_t* __restrict__ BPp,
        const float* __restrict__ biasvp, unsigned sigmaskp,
        const float* __restrict__ mulp, int ldmul,
        const float* __restrict__ addp, int ldadd,
        float* __restrict__ Cp, int M, int N, int K,
        const ushort_t* AH2, const ushort_t* AL2, const ushort_t* BP2,
        const float* biasv2, unsigned sigmask2, float* C2, int nsplit){
    extern __shared__ __align__(16) ushort_t sh[];
    const ushort_t* AH = AHp; const ushort_t* AL = ALp; const ushort_t* BP = BPp;
    const float* biasv = biasvp; unsigned sigmask = sigmaskp; float* C = Cp;
    int bx = blockIdx.x;
    if (AH2 && bx >= nsplit){
        AH = AH2; AL = AL2; BP = BP2; biasv = biasv2; sigmask = sigmask2; C = C2;
        bx -= nsplit;
    }
    int n0 = bx*128, m0 = blockIdx.y*64;
    int tid = threadIdx.x, lane = tid&31, wid = tid>>5;
    int g = lane>>2, tig = lane&3;
    int wm = (wid&1)*32, wn = (wid>>1)*32;
    float acc[2][4][4] = {};
    const int nit = K>>5;
    unsigned sbase = (unsigned)__cvta_generic_to_shared(sh);

    // A cp.async mapping (non-GLU)
    int apl_ = tid>>7, ac = tid&127;
    int arow1 = ac>>2, aq = ac&3;
    int arow2 = arow1 + 32;
    const ushort_t* AsrcP = 0;
    unsigned adst1 = 0, adst2 = 0;
    // A register path (GLU)
    int ar = tid>>2, akq = tid&3;
    const float *Apf = 0, *Gpf = 0;
    if (GLU){
        Apf = Af + (size_t)(m0+ar)*ldaf;
        Gpf = A2f + (size_t)(m0+ar)*ldaf;
    } else {
        AsrcP = (apl_ ? AL : AH) + (size_t)m0*lda;
        adst1 = (unsigned)((apl_*APL + arow1*AS_ + aq*8)*2);
        adst2 = (unsigned)((apl_*APL + arow2*AS_ + aq*8)*2);
    }
    // B cp.async mapping
    int bpl = tid>>7, bcid = tid&127;
    int brow = bcid>>4, bseg = (bcid&15)*8;
    const ushort_t* BsrcP = BP + (size_t)bpl*K*N + n0 + bseg;
    unsigned bdstb = (unsigned)((2*APL + bpl*BPL + bseg)*2);

    auto issue_tile = [&](int it){
        unsigned nb = (unsigned)((it&1)*BUFH*2);
        int kb = it*32;
        if (!GLU){
            cp16(sbase + nb + adst1, AsrcP + (size_t)(arow1)*lda + kb + aq*8);
            cp16(sbase + nb + adst2, AsrcP + (size_t)(arow2)*lda + kb + aq*8);
        }
        #pragma unroll
        for (int rr=0; rr<4; rr++){
            int kr = brow + rr*8;
            cp16(sbase + nb + bdstb + (unsigned)(kr*BSr*2),
                 BsrcP + (size_t)(kb + kr)*N);
        }
        CP_COMMIT();
    };
    auto store_A_glu = [&](int it){
        ushort_t* base = sh + (it&1)*BUFH;
        #pragma unroll
        for (int q=0; q<2; q++){
            int koff = it*32 + akq*4 + q*16;
            float4 v  = *(const float4*)(Apf + koff);
            float4 gv = *(const float4*)(Gpf + koff);
            v.x = v.x*sigm(v.x)*gv.x; v.y = v.y*sigm(v.y)*gv.y;
            v.z = v.z*sigm(v.z)*gv.z; v.w = v.w*sigm(v.w)*gv.w;
            unsigned h01,l01,h23,l23;
            split2(v.x,v.y,h01,l01);
            split2(v.z,v.w,h23,l23);
            int so = ar*AS_ + akq*4 + q*16;
            *(unsigned*)(base + so)           = h01;
            *(unsigned*)(base + so + 2)       = h23;
            *(unsigned*)(base + APL + so)     = l01;
            *(unsigned*)(base + APL + so + 2) = l23;
        }
    };

    // prologue
    issue_tile(0); if (GLU) store_A_glu(0);
    CP_WAIT0();
    __syncthreads();

    // ldmatrix per-thread byte offsets
    int mi = lane>>3, r8 = lane&7;
    unsigned aoff0 = (unsigned)(((wm + (mi&1)*8 + r8)*AS_ + (mi>>1)*8)*2);
    unsigned aoff1 = aoff0 + (unsigned)(16*AS_*2);
    unsigned boff0 = (unsigned)((((mi&1)*8 + r8)*BSr + wn + (mi>>1)*8)*2);
    unsigned boff1 = boff0 + 32;

    for (int it=0; it<nit; it++){
        if (it+1 < nit){
            issue_tile(it+1);
            if (GLU) store_A_glu(it+1);
        }
        unsigned bufb = sbase + (unsigned)((it&1)*BUFH*2);
        #pragma unroll
        for (int ks=0; ks<2; ks++){
            unsigned ka = bufb + (unsigned)(ks*32);
            unsigned kb = bufb + (unsigned)(ks*16*BSr*2);
            unsigned ah[2][4], alo[2][4], bh[2][4], bl[2][4];
            ldsm_x4(ah[0],  ka + aoff0);
            ldsm_x4(ah[1],  ka + aoff1);
            ldsm_x4(alo[0], ka + (unsigned)(APL*2) + aoff0);
            ldsm_x4(alo[1], ka + (unsigned)(APL*2) + aoff1);
            ldsm_x4_t(bh[0], kb + (unsigned)(2*APL*2) + boff0);
            ldsm_x4_t(bh[1], kb + (unsigned)(2*APL*2) + boff1);
            ldsm_x4_t(bl[0], kb + (unsigned)((2*APL+BPL)*2) + boff0);
            ldsm_x4_t(bl[1], kb + (unsigned)((2*APL+BPL)*2) + boff1);
            #pragma unroll
            for (int mt=0; mt<2; mt++){
                #pragma unroll
                for (int nt=0; nt<4; nt++){
                    const unsigned* bph = &bh[nt>>1][(nt&1)*2];
                    const unsigned* bpl_ = &bl[nt>>1][(nt&1)*2];
                    mma_bf16(acc[mt][nt], ah[mt],  bph);
                    mma_bf16(acc[mt][nt], ah[mt],  bpl_);
                    mma_bf16(acc[mt][nt], alo[mt], bph);
                }
            }
        }
        if (it+1 < nit) CP_WAIT0();
        __syncthreads();
    }

    // epilogue
    #pragma unroll
    for (int mt=0; mt<2; mt++){
        #pragma unroll
        for (int nt=0; nt<4; nt++){
            int row0 = m0 + wm + mt*16 + g;
            int row1 = row0 + 8;
            int col  = n0 + wn + nt*8 + 2*tig;
            float b0 = biasv ? biasv[col]   : 0.f;
            float b1 = biasv ? biasv[col+1] : 0.f;
            float e0 = acc[mt][nt][0] + b0, e1 = acc[mt][nt][1] + b1;
            float e2 = acc[mt][nt][2] + b0, e3 = acc[mt][nt][3] + b1;
            if ((sigmask >> (col>>7)) & 1u){ e0=sigm(e0); e1=sigm(e1); e2=sigm(e2); e3=sigm(e3); }
            size_t o0 = (size_t)row0*N + col, o1 = (size_t)row1*N + col;
            if (mulp){
                size_t u0 = (size_t)row0*ldmul + col, u1 = (size_t)row1*ldmul + col;
                e0*=mulp[u0]; e1*=mulp[u0+1]; e2*=mulp[u1]; e3*=mulp[u1+1];
            }
            if (addp){
                size_t u0 = (size_t)row0*ldadd + col, u1 = (size_t)row1*ldadd + col;
                e0+=addp[u0]; e1+=addp[u0+1]; e2+=addp[u1]; e3+=addp[u1+1];
            }
            *(float2*)&C[o0] = make_float2(e0,e1);
            *(float2*)&C[o1] = make_float2(e2,e3);
        }
    }
}

// ---------------- K6: windowed attention ----------------
__global__ void attn_kernel(int blk){
    __shared__ float qs[NQ*DD];
    __shared__ float kv[NK*33];
    __shared__ float lb[NQ*129];
    int w = blockIdx.x, h = blockIdx.y, b = blockIdx.z;
    int tid = threadIdx.x;
    size_t tokbase = (size_t)b*NN + (size_t)w*NQ;
    int kstart = w*NQ - 48;
    for (int i=tid; i<NQ*DD; i+=256){
        int r=i>>5, c=i&31;
        qs[i] = g_qkvg[(tokbase+r)*512 + h*DD + c];
    }
    for (int i=tid; i<NK*DD; i+=256){
        int r=i>>5, c=i&31;
        int src = kstart + r; src = min(max(src,0), NN-1);
        kv[r*33+c] = g_qkvg[((size_t)b*NN + src)*512 + 128 + h*DD + c];
    }
    const float* plane = g_biasbuf + ((size_t)blk*HH + h)*(size_t)ROWS;
    size_t rb = (((size_t)b*WW + w)*NQ)*NK;
    for (int i=tid; i<NQ*NK; i+=256){
        int q=i>>7, k=i&127;
        lb[q*129+k] = plane[rb + i];
    }
    __syncthreads();
    {
        int qt = tid>>5, kt = tid&31;
        float acc[4][4] = {};
        #pragma unroll
        for (int d=0; d<DD; d++){
            float qa[4], kb[4];
            #pragma unroll
            for (int j=0;j<4;j++) qa[j] = qs[(qt*4+j)*DD + d];
            #pragma unroll
            for (int l=0;l<4;l++) kb[l] = kv[(kt+32*l)*33 + d];
            #pragma unroll
            for (int j=0;j<4;j++)
                #pragma unroll
                for (int l=0;l<4;l++) acc[j][l] += qa[j]*kb[l];
        }
        const float isd = 0.17677669529663687f;
        #pragma unroll
        for (int j=0;j<4;j++){
            #pragma unroll
            for (int l=0;l<4;l++){
                int q = qt*4+j, k = kt+32*l;
                int src = kstart + k;
                float v = (src>=0 && src<NN) ? acc[j][l]*isd + lb[q*129+k] : -1e9f;
                lb[q*129+k] = v;
            }
        }
    }
    __syncthreads();
    for (int i=tid; i<NK*DD; i+=256){
        int r=i>>5, c=i&31;
        int src = kstart + r; src = min(max(src,0), NN-1);
        kv[r*33+c] = g_qkvg[((size_t)b*NN + src)*512 + 256 + h*DD + c];
    }
    {
        int wid = tid>>5, lane = tid&31;
        for (int rq=0; rq<4; rq++){
            int q = wid*4 + rq;
            float m = -1e30f;
            #pragma unroll
            for (int k=lane; k<NK; k+=32) m = fmaxf(m, lb[q*129+k]);
            #pragma unroll
            for (int o=16;o;o>>=1) m = fmaxf(m, __shfl_xor_sync(0xffffffffu, m, o));
            float ssum = 0.f;
            #pragma unroll
            for (int k=lane; k<NK; k+=32){
                float e = __expf(lb[q*129+k] - m);
                lb[q*129+k] = e; ssum += e;
            }
            #pragma unroll
            for (int o=16;o;o>>=1) ssum += __shfl_xor_sync(0xffffffffu, ssum, o);
            float invs = 1.f/ssum;
            #pragma unroll
            for (int k=lane; k<NK; k+=32) lb[q*129+k] *= invs;
        }
    }
    __syncthreads();
    {
        int qp = tid>>4, dp = tid&15;
        float av[2][2] = {};
        #pragma unroll 4
        for (int k=0;k<NK;k++){
            float p0 = lb[(qp*2  )*129 + k];
            float p1 = lb[(qp*2+1)*129 + k];
            float v0 = kv[k*33 + dp];
            float v1 = kv[k*33 + dp + 16];
            av[0][0]+=p0*v0; av[0][1]+=p0*v1; av[1][0]+=p1*v0; av[1][1]+=p1*v1;
        }
        #pragma unroll
        for (int a2=0;a2<2;a2++){
            #pragma unroll
            for (int b2=0;b2<2;b2++){
                int q = qp*2+a2, d = dp+16*b2;
                float gate = g_qkvg[(tokbase+q)*512 + 384 + h*DD + d];
                float v = gate*av[a2][b2];
                size_t off = (tokbase+q)*CA + h*DD + d;
                ushort_t hh,ll;
                split1(v,hh,ll);
                g_attH[off]=hh; g_attL[off]=ll;
            }
        }
    }
}

// ---------------- host launcher ----------------
extern "C" void kernel_launch(void* const* d_in, const int* in_sizes, int n_in,
                              void* d_out, int out_size){
    const float* q_in   = (const float*)d_in[0];
    const float* s_in   = (const float*)d_in[1];
    const float* p_in   = (const float*)d_in[2];
    const float* adaln_scale_w = (const float*)d_in[3];
    const float* adaln_scale_b = (const float*)d_in[4];
    const float* adaln_shift_w = (const float*)d_in[5];
    const float* wq = (const float*)d_in[6];
    const float* bq = (const float*)d_in[7];
    const float* wk = (const float*)d_in[8];
    const float* wv = (const float*)d_in[9];
    const float* lnz_w = (const float*)d_in[10];
    const float* lnz_b = (const float*)d_in[11];
    const float* wb_pair = (const float*)d_in[12];
    const float* wg = (const float*)d_in[13];
    const float* wo = (const float*)d_in[14];
    const float* sgate_w = (const float*)d_in[15];
    const float* sgate_b = (const float*)d_in[16];
    const float* t_scale_w = (const float*)d_in[17];
    const float* t_scale_b = (const float*)d_in[18];
    const float* t_shift_w = (const float*)d_in[19];
    const float* t_wa = (const float*)d_in[20];
    const float* t_wb = (const float*)d_in[21];
    const float* t_wo = (const float*)d_in[22];
    const float* t_sgate_w = (const float*)d_in[23];
    const float* t_sgate_b = (const float*)d_in[24];
    float* out = (float*)d_out;

    ushort_t *p_slnH,*p_slnL,*p_alnH,*p_alnL,*p_tlnH,*p_tlnL,*p_attH,*p_attL;
    ushort_t *p_wgateP,*p_wqkvgP,*p_whidP,*p_wwoP,*p_wtwoP;
    float *p_gatesP,*p_qkvg,*p_ao,*p_a,*p_hid,*p_bgate,*p_bqkvg;
    cudaGetSymbolAddress((void**)&p_slnH, g_slnH);
    cudaGetSymbolAddress((void**)&p_slnL, g_slnL);
    cudaGetSymbolAddress((void**)&p_alnH, g_alnH);
    cudaGetSymbolAddress((void**)&p_alnL, g_alnL);
    cudaGetSymbolAddress((void**)&p_tlnH, g_tlnH);
    cudaGetSymbolAddress((void**)&p_tlnL, g_tlnL);
    cudaGetSymbolAddress((void**)&p_attH, g_attH);
    cudaGetSymbolAddress((void**)&p_attL, g_attL);
    cudaGetSymbolAddress((void**)&p_wgateP, g_wgateP);
    cudaGetSymbolAddress((void**)&p_wqkvgP, g_wqkvgP);
    cudaGetSymbolAddress((void**)&p_whidP,  g_whidP);
    cudaGetSymbolAddress((void**)&p_wwoP,   g_wwoP);
    cudaGetSymbolAddress((void**)&p_wtwoP,  g_wtwoP);
    cudaGetSymbolAddress((void**)&p_gatesP, g_gatesP);
    cudaGetSymbolAddress((void**)&p_qkvg,   g_qkvg);
    cudaGetSymbolAddress((void**)&p_ao,     g_ao);
    cudaGetSymbolAddress((void**)&p_a,      g_a);
    cudaGetSymbolAddress((void**)&p_hid,    g_hid);
    cudaGetSymbolAddress((void**)&p_bgate,  g_bgate);
    cudaGetSymbolAddress((void**)&p_bqkvg,  g_bqkvg);

    cudaFuncSetAttribute(gemm_kernel<false>, cudaFuncAttributeMaxDynamicSharedMemorySize, GEMM_SMEM);
    cudaFuncSetAttribute(gemm_kernel<true>,  cudaFuncAttributeMaxDynamicSharedMemorySize, GEMM_SMEM);

    // side stream + fork/join events (host-side resources; created once, reused;
    // only the record/wait ops appear in the graph)
    static cudaStream_t s2 = 0;
    static cudaEvent_t ev_fork = 0, ev_join = 0;
    if (!s2){
        cudaStreamCreateWithFlags(&s2, cudaStreamNonBlocking);
        cudaEventCreateWithFlags(&ev_fork, cudaEventDisableTiming);
        cudaEventCreateWithFlags(&ev_join, cudaEventDisableTiming);
    }

    const ushort_t* U0 = (const ushort_t*)0;
    const float*    F0 = (const float*)0;

    // fork: bias_kernel (memory-bound) runs on s2 concurrently with the
    // tensor-bound stage-0 chain on the main stream.
    cudaEventRecord(ev_fork, 0);
    cudaStreamWaitEvent(s2, ev_fork, 0);
    bias_kernel<<<ROWS/256,256,0,s2>>>(p_in, lnz_w, lnz_b, wb_pair);
    cudaEventRecord(ev_join, s2);

    // main stream: stage 0 compute chain
    {
        int total = CS*NG + 2*NB*128*512 + NB*128*128 + NB*256*128 + NG + NB*512;
        pack_kernel<<<(total+255)/256,256>>>(adaln_scale_w, adaln_shift_w, sgate_w,
            t_scale_w, t_shift_w, t_sgate_w,
            adaln_scale_b, sgate_b, t_scale_b, t_sgate_b,
            wq, bq, wk, wv, wg, t_wa, t_wb, wo, t_wo);
    }
    sln_kernel<<<TT,128>>>(s_in);
    gemm_kernel<false><<<dim3(NG/128, TT/64),256,GEMM_SMEM>>>(
        p_slnH, p_slnL, CS, F0, F0, 0,
        p_wgateP, p_bgate, (0x2Du)|(0x2Du<<6)|(0x2Du<<12),
        F0, 0, F0, 0, p_gatesP, TT, NG, CS,
        U0, U0, U0, F0, 0u, (float*)0, 1<<30);

    // stage 1
    const float* acur = q_in;
    for (int i=0;i<NB;i++){
        lnmod_kernel<<<TT,128>>>(acur, i);
        // fused qkvg (bx<4) + hid (bx>=4), both [TT,512], K=128
        gemm_kernel<false><<<dim3(8, TT/64),256,GEMM_SMEM>>>(
            p_alnH, p_alnL, CA, F0, F0, 0,
            p_wqkvgP + (size_t)i*2*128*512, p_bqkvg + i*512, 8u,
            F0, 0, F0, 0, p_qkvg, TT, 512, CA,
            p_tlnH, p_tlnL, p_whidP + (size_t)i*2*128*512, F0, 0u, p_hid, 4);
        if (i == 0){
            // join: attention needs biasbuf
            cudaStreamWaitEvent(0, ev_join, 0);
        }
        attn_kernel<<<dim3(WW,HH,Bb),256>>>(i);
        gemm_kernel<false><<<dim3(1, TT/64),256,GEMM_SMEM>>>(
            p_attH, p_attL, CA, F0, F0, 0,
            p_wwoP + (size_t)i*2*128*128, F0, 0u,
            p_gatesP + (size_t)(i*6+2)*128, NG, F0, 0, p_ao, TT, CA, CA,
            U0, U0, U0, F0, 0u, (float*)0, 1<<30);
        float* dst = (i==NB-1) ? out : p_a;
        gemm_kernel<true><<<dim3(1, TT/64),256,GEMM_SMEM>>>(
            U0, U0, 0, p_hid, p_hid + 256, 512,
            p_wtwoP + (size_t)i*2*256*128, F0, 0u,
            p_gatesP + (size_t)(i*6+5)*128, NG, p_ao, CA, dst, TT, CA, HID,
            U0, U0, U0, F0, 0u, (float*)0, 1<<30);
        acur = p_a;
    }
    (void)in_sizes; (void)n_in; (void)out_size;
}